// round 11
// baseline (speedup 1.0000x reference)
#include <cuda_runtime.h>
#include <cuda_bf16.h>

#define CH 96
#define HH 128
#define WW 128
#define BC 1536
#define NF 129

// digit-reversed base-4 position (involution: P16(P16(k)) == k)
#define P16(k) ((((k) & 3) << 2) | ((k) >> 2))

// Kf stored permuted: float4-vectorized, [c][f][j][slot/2], slot s holds
// spectral bin m = 16*P16(s) + j  (so register-linear multiply in fused).
__device__ float4 g_KfV[CH * NF * 128];

#define TILE_N 16512                     // 128 rows * 129 bins (float2)
#define TP     129                       // tile pitch in float2 (odd -> conflict-free)
#define GROUPS 32
#define SCR_F2 (GROUPS * 256)            // per-group 16x16 float2, rotation swizzle
#define SMEM_BYTES ((TILE_N + SCR_F2) * 8)   // 197632 B

// ---------------------------------------------------------------------------
template<int SGN>
__device__ __forceinline__ void fft4(float& r0, float& i0, float& r1, float& i1,
                                     float& r2, float& i2, float& r3, float& i3) {
    float t0r = r0 + r2, t0i = i0 + i2, t1r = r0 - r2, t1i = i0 - i2;
    float t2r = r1 + r3, t2i = i1 + i3, t3r = r1 - r3, t3i = i1 - i3;
    float w3r = (SGN < 0) ? t3i : -t3i;
    float w3i = (SGN < 0) ? -t3r : t3r;
    r0 = t0r + t2r; i0 = t0i + t2i;
    r2 = t0r - t2r; i2 = t0i - t2i;
    r1 = t1r + w3r; i1 = t1i + w3i;
    r3 = t1r - w3r; i3 = t1i - w3i;
}

// In-register 16-point DFT. PIN=false: natural input, X[k] lands at P16(k).
// PIN=true: input stored in P16 layout, output lands in natural order.
template<int SGN, bool PIN>
__device__ __forceinline__ void fft16(float* r, float* im) {
#define IXQ(n) (PIN ? ((((n) & 3) << 2) | (((n) >> 2) & 3)) : (n))
    #pragma unroll
    for (int b = 0; b < 4; b++)
        fft4<SGN>(r[IXQ(b)], im[IXQ(b)], r[IXQ(b+4)], im[IXQ(b+4)],
                  r[IXQ(b+8)], im[IXQ(b+8)], r[IXQ(b+12)], im[IXQ(b+12)]);
    const float TC[10] = {1.f, 0.92387953f, 0.70710678f, 0.38268343f, 0.f,
                          0.f, -0.70710678f, 0.f, 0.f, -0.92387953f};
    const float TS[10] = {0.f, 0.38268343f, 0.70710678f, 0.92387953f, 1.f,
                          0.f, 0.70710678f, 0.f, 0.f, -0.38268343f};
    #pragma unroll
    for (int k1 = 1; k1 < 4; k1++)
        #pragma unroll
        for (int b = 1; b < 4; b++) {
            const int m = k1 * b, p = IXQ(4*k1 + b);
            const float c = TC[m], s = (float)SGN * TS[m];
            float vr = r[p] * c - im[p] * s;
            im[p]    = r[p] * s + im[p] * c;
            r[p]     = vr;
        }
    #pragma unroll
    for (int k1 = 0; k1 < 4; k1++)
        fft4<SGN>(r[IXQ(4*k1)], im[IXQ(4*k1)], r[IXQ(4*k1+1)], im[IXQ(4*k1+1)],
                  r[IXQ(4*k1+2)], im[IXQ(4*k1+2)], r[IXQ(4*k1+3)], im[IXQ(4*k1+3)]);
#undef IXQ
}

// 256-pt FFT by one 16-thread group. Single-pass float2 transpose through a
// 16x16 rotation-swizzled scratch (element (r,c) at idx 16r + ((c+r)&15)):
// conflict-free in both write and read phases, no padding.
template<int SGN, bool PIN>
__device__ __forceinline__ void fft256s(float* zr, float* zi, float2* sc, int j) {
    fft16<SGN, PIN>(zr, zi);
    float wjs, wjc;
    __sincosf((float)SGN * (6.2831853071795864f / 256.f) * (float)j, &wjs, &wjc);
    float wr = 1.f, wi = 0.f;
    #pragma unroll
    for (int k1 = 0; k1 < 16; k1++) {
        const int p = PIN ? k1 : P16(k1);       // X[k1] position after fft16
        sc[k1 * 16 + ((j + k1) & 15)] =
            make_float2(zr[p] * wr - zi[p] * wi, zr[p] * wi + zi[p] * wr);
        float nr = wr * wjc - wi * wjs;
        wi = wr * wjs + wi * wjc; wr = nr;
    }
    __syncwarp();
    #pragma unroll
    for (int n2 = 0; n2 < 16; n2++) {
        const float2 v = sc[j * 16 + ((n2 + j) & 15)];
        zr[n2] = v.x; zi[n2] = v.y;
    }
    __syncwarp();
    fft16<SGN, false>(zr, zi);
}

// Unpack a packed-real forward FFT (Z of A+iB) and write bins 0..128 of rows
// baseA/baseB into the float2 tile.
__device__ __forceinline__ void unpack_rows_to_tile(
    const float* zr, const float* zi, float2* tile, int baseA, int baseB, int j) {
    #pragma unroll
    for (int k2 = 0; k2 < 8; k2++) {
        float sr_ = zr[P16(15 - k2)], si_ = zi[P16(15 - k2)];
        float mr_ = __shfl_sync(0xffffffffu, sr_, (16 - j) & 15, 16);
        float mi_ = __shfl_sync(0xffffffffu, si_, (16 - j) & 15, 16);
        if (j == 0) { mr_ = zr[P16((16 - k2) & 15)]; mi_ = zi[P16((16 - k2) & 15)]; }
        const float zkr = zr[P16(k2)], zki = zi[P16(k2)];
        tile[baseA + k2*16 + j] = make_float2(0.5f * (zkr + mr_), 0.5f * (zki - mi_));
        tile[baseB + k2*16 + j] = make_float2(0.5f * (zki + mi_), 0.5f * (mr_ - zkr));
    }
    if (j == 0) {                              // bin 128 (self-mirror, real)
        tile[baseA + 128] = make_float2(zr[P16(8)], 0.f);
        tile[baseB + 128] = make_float2(zi[P16(8)], 0.f);
    }
}

// ---------------------------------------------------------------------------
// kprep: one block per channel. MLP + packed row rFFTs -> tile, column FFTs
// -> g_KfV (cols 0 & 128 packed as one complex FFT; permuted slot layout).
// ---------------------------------------------------------------------------
__global__ void __launch_bounds__(512)
kprep_kernel(const float* __restrict__ W1, const float* __restrict__ b1,
             const float* __restrict__ W2, const float* __restrict__ b2) {
    extern __shared__ float2 smem2[];
    float2* tile = smem2;
    float2* sc   = smem2 + TILE_N + (threadIdx.x >> 4) * 256;
    const int t = threadIdx.x, g = t >> 4, j = t & 15;
    const int c = blockIdx.x;

    float w1a[16], w1b[16], bb1[16], w2[16];
    #pragma unroll
    for (int h = 0; h < 16; h++) {
        w1a[h] = W1[h]; w1b[h] = W1[16 + h]; bb1[h] = b1[h]; w2[h] = W2[h * CH + c];
    }
    const float bias = b2[c];

    // Phase 1: 64 packed row FFTs (rows r, r+64), 2 iters
    #pragma unroll 1
    for (int it = 0; it < 2; it++) {
        const int rA = it * 32 + g, rB = rA + 64;
        const float gyA = (float)rA * (1.f / 127.f);
        const float gyB = (float)rB * (1.f / 127.f);
        float zr[16], zi[16];
        #pragma unroll
        for (int n1 = 0; n1 < 16; n1++) {
            const int col = n1 * 16 + j;
            float vA = 0.f, vB = 0.f;
            if (col < 128) {
                const float gx = (float)col * (1.f / 127.f);
                vA = bias; vB = bias;
                #pragma unroll
                for (int h = 0; h < 16; h++) {
                    const float gxw = gx * w1b[h] + bb1[h];
                    vA += fmaxf(gyA * w1a[h] + gxw, 0.f) * w2[h];
                    vB += fmaxf(gyB * w1a[h] + gxw, 0.f) * w2[h];
                }
            }
            zr[n1] = vA; zi[n1] = vB;
        }
        fft256s<-1, false>(zr, zi, sc, j);
        unpack_rows_to_tile(zr, zi, tile, rA * TP, rB * TP, j);
    }
    __syncthreads();

    // Phase 2: 128 column tasks (task 0 = packed cols 0&128), 4 iters
    #pragma unroll 1
    for (int it = 0; it < 4; it++) {
        const int f = it * 32 + g;
        float zr[16], zi[16];
        #pragma unroll
        for (int n1 = 0; n1 < 8; n1++) {         // rows >= 128 are zero pad
            const int row = n1 * 16 + j;
            if (f == 0) { zr[n1] = tile[row * TP].x; zi[n1] = tile[row * TP + 128].x; }
            else        { const float2 v = tile[row * TP + f]; zr[n1] = v.x; zi[n1] = v.y; }
        }
        #pragma unroll
        for (int n1 = 8; n1 < 16; n1++) { zr[n1] = 0.f; zi[n1] = 0.f; }
        fft256s<-1, false>(zr, zi, sc, j);

        if (f == 0) {
            // unpack hermitian halves into slot-ordered arrays, store cols 0,128
            float ar[16], ai[16], br[16], bi[16];
            #pragma unroll
            for (int k2 = 0; k2 < 16; k2++) {
                const int p = P16(k2);
                float sr_ = zr[P16(15 - k2)], si_ = zi[P16(15 - k2)];
                float mr_ = __shfl_sync(0xffffu, sr_, (16 - j) & 15, 16);
                float mi_ = __shfl_sync(0xffffu, si_, (16 - j) & 15, 16);
                if (j == 0) { mr_ = zr[P16((16 - k2) & 15)]; mi_ = zi[P16((16 - k2) & 15)]; }
                ar[p] = 0.5f * (zr[p] + mr_);  ai[p] = 0.5f * (zi[p] - mi_);
                br[p] = 0.5f * (zi[p] + mi_);  bi[p] = 0.5f * (mr_ - zr[p]);
            }
            float4* K0 = g_KfV + (c * NF +   0) * 128 + j * 8;
            float4* KN = g_KfV + (c * NF + 128) * 128 + j * 8;
            #pragma unroll
            for (int v = 0; v < 8; v++) {
                K0[v] = make_float4(ar[2*v], ai[2*v], ar[2*v+1], ai[2*v+1]);
                KN[v] = make_float4(br[2*v], bi[2*v], br[2*v+1], bi[2*v+1]);
            }
        } else {
            float4* KP = g_KfV + (c * NF + f) * 128 + j * 8;
            #pragma unroll
            for (int v = 0; v < 8; v++)
                KP[v] = make_float4(zr[2*v], zi[2*v], zr[2*v+1], zi[2*v+1]);
        }
    }
}

// ---------------------------------------------------------------------------
// Fused per-image kernel: 512 threads = 32 groups, one block per image.
// ---------------------------------------------------------------------------
__global__ void __launch_bounds__(512)
fused_kernel(const float* __restrict__ x, float* __restrict__ out) {
    extern __shared__ float2 smem2[];
    float2* tile = smem2;
    float2* sc   = smem2 + TILE_N + (threadIdx.x >> 4) * 256;
    const int t = threadIdx.x, g = t >> 4, j = t & 15;
    const int bc = blockIdx.x;
    const int c  = bc % CH;

    // ---- Phase 1: 64 packed row rFFTs, 2 iters ----
    #pragma unroll 1
    for (int it = 0; it < 2; it++) {
        const int rA = it * 32 + g, rB = rA + 64;
        const int xa = (bc * HH + rA) * WW;
        const int xb = (bc * HH + rB) * WW;
        float zr[16], zi[16];
        #pragma unroll
        for (int n1 = 0; n1 < 16; n1++) {
            const int col = n1 * 16 + j;
            if (col < 128) { zr[n1] = x[xa + col]; zi[n1] = x[xb + col]; }
            else           { zr[n1] = 0.f;         zi[n1] = 0.f; }
        }
        fft256s<-1, false>(zr, zi, sc, j);
        unpack_rows_to_tile(zr, zi, tile, rA * TP, rB * TP, j);
    }
    __syncthreads();

    // ---- Phase 2: 128 column tasks (task 0 = packed cols 0&128), 4 iters ----
    #pragma unroll 1
    for (int it = 0; it < 4; it++) {
        const int f = it * 32 + g;
        float zr[16], zi[16];
        #pragma unroll
        for (int n1 = 0; n1 < 8; n1++) {         // rows >= 128 are zero pad
            const int row = n1 * 16 + j;
            if (f == 0) { zr[n1] = tile[row * TP].x; zi[n1] = tile[row * TP + 128].x; }
            else        { const float2 v = tile[row * TP + f]; zr[n1] = v.x; zi[n1] = v.y; }
        }
        #pragma unroll
        for (int n1 = 8; n1 < 16; n1++) { zr[n1] = 0.f; zi[n1] = 0.f; }
        fft256s<-1, false>(zr, zi, sc, j);       // forward along column

        if (f == 0) {
            float k0r[16], k0i[16], knr[16], kni[16];
            const float4* K0 = g_KfV + (c * NF +   0) * 128 + j * 8;
            const float4* KN = g_KfV + (c * NF + 128) * 128 + j * 8;
            #pragma unroll
            for (int v = 0; v < 8; v++) {
                const float4 a = K0[v], b = KN[v];
                k0r[2*v] = a.x; k0i[2*v] = a.y; k0r[2*v+1] = a.z; k0i[2*v+1] = a.w;
                knr[2*v] = b.x; kni[2*v] = b.y; knr[2*v+1] = b.z; kni[2*v+1] = b.w;
            }
            float or_[16], oi_[16];              // snapshot (mirror needs pre-mult)
            #pragma unroll
            for (int q = 0; q < 16; q++) { or_[q] = zr[q]; oi_[q] = zi[q]; }
            #pragma unroll
            for (int k2 = 0; k2 < 16; k2++) {
                const int p = P16(k2);
                float mr_ = __shfl_sync(0xffffu, or_[P16(15 - k2)], (16 - j) & 15, 16);
                float mi_ = __shfl_sync(0xffffu, oi_[P16(15 - k2)], (16 - j) & 15, 16);
                if (j == 0) { mr_ = or_[P16((16 - k2) & 15)]; mi_ = oi_[P16((16 - k2) & 15)]; }
                const float Ar = 0.5f * (or_[p] + mr_), Ai = 0.5f * (oi_[p] - mi_);
                const float Br = 0.5f * (oi_[p] + mi_), Bi = 0.5f * (mr_ - or_[p]);
                const float Cr = Ar * k0r[p] - Ai * k0i[p], Ci = Ar * k0i[p] + Ai * k0r[p];
                const float Dr = Br * knr[p] - Bi * kni[p], Di = Br * kni[p] + Bi * knr[p];
                zr[p] = Cr - Di;                 // repack: Y = C + i*D
                zi[p] = Ci + Dr;
            }
        } else {
            float kr[16], ki[16];
            const float4* KP = g_KfV + (c * NF + f) * 128 + j * 8;
            #pragma unroll
            for (int v = 0; v < 8; v++) {
                const float4 a = KP[v];
                kr[2*v] = a.x; ki[2*v] = a.y; kr[2*v+1] = a.z; ki[2*v+1] = a.w;
            }
            #pragma unroll
            for (int q = 0; q < 16; q++) {       // register-linear multiply
                const float a = zr[q], b = zi[q];
                zr[q] = a * kr[q] - b * ki[q];
                zi[q] = a * ki[q] + b * kr[q];
            }
        }
        fft256s<1, true>(zr, zi, sc, j);         // unnormalized inverse (PIN input)
        if (f == 0) {
            #pragma unroll
            for (int k2 = 0; k2 < 8; k2++) {     // keep rows 0..127; cols real
                const int row = k2 * 16 + j;
                tile[row * TP]       = make_float2(zr[P16(k2)], 0.f);
                tile[row * TP + 128] = make_float2(zi[P16(k2)], 0.f);
            }
        } else {
            #pragma unroll
            for (int k2 = 0; k2 < 8; k2++) {
                const int row = k2 * 16 + j;
                tile[row * TP + f] = make_float2(zr[P16(k2)], zi[P16(k2)]);
            }
        }
    }
    __syncthreads();

    // ---- Phase 3: 64 packed hermitian row inverses + residual, 2 iters ----
    #pragma unroll 1
    for (int it = 0; it < 2; it++) {
        const int rA = it * 32 + g, rB = rA + 64;
        const int baseA = rA * TP, baseB = rB * TP;
        float zr[16], zi[16];
        #pragma unroll
        for (int n1 = 0; n1 < 16; n1++) {
            const int n = n1 * 16 + j;
            float Ar, Ai, Br, Bi;
            if (n <= 128) {
                const float2 vA = tile[baseA + n], vB = tile[baseB + n];
                Ar = vA.x; Ai = vA.y; Br = vB.x; Bi = vB.y;
            } else {
                const int m2 = 256 - n;           // hermitian mirror
                const float2 vA = tile[baseA + m2], vB = tile[baseB + m2];
                Ar = vA.x; Ai = -vA.y; Br = vB.x; Bi = -vB.y;
            }
            zr[n1] = Ar - Bi;                     // Z = A + i*B
            zi[n1] = Ai + Br;
        }
        fft256s<1, false>(zr, zi, sc, j);         // z[n] = a[n] + i*b[n]
        const int ga = (bc * HH + rA) * WW;
        const int gb = (bc * HH + rB) * WW;
        #pragma unroll
        for (int k2 = 0; k2 < 8; k2++) {
            const int col = k2 * 16 + j;
            out[ga + col] = zr[P16(k2)] + x[ga + col];
            out[gb + col] = zi[P16(k2)] + x[gb + col];
        }
    }
}

// ---------------------------------------------------------------------------
extern "C" void kernel_launch(void* const* d_in, const int* in_sizes, int n_in,
                              void* d_out, int out_size) {
    const float* x  = (const float*)d_in[0];
    const float* W1 = (const float*)d_in[1];
    const float* b1 = (const float*)d_in[2];
    const float* W2 = (const float*)d_in[3];
    const float* b2 = (const float*)d_in[4];
    float* out = (float*)d_out;

    static int smem_set = 0;
    if (!smem_set) {
        cudaFuncSetAttribute(kprep_kernel,
                             cudaFuncAttributeMaxDynamicSharedMemorySize, SMEM_BYTES);
        cudaFuncSetAttribute(fused_kernel,
                             cudaFuncAttributeMaxDynamicSharedMemorySize, SMEM_BYTES);
        smem_set = 1;
    }

    kprep_kernel<<<CH, 512, SMEM_BYTES>>>(W1, b1, W2, b2);
    fused_kernel<<<BC, 512, SMEM_BYTES>>>(x, out);
}

// round 12
// speedup vs baseline: 1.2149x; 1.2149x over previous
#include <cuda_runtime.h>
#include <cuda_bf16.h>

#define CH 96
#define HH 128
#define WW 128
#define BC 1536
#define NF 129

// digit-reversed base-4 position (involution: P16(P16(k)) == k)
#define P16(k) ((((k) & 3) << 2) | ((k) >> 2))

__device__ float2 g_Kf[CH * NF * 256];       // full 2D FFT of k  [c][f][m]

#define TILE_N 16512                         // 128 rows * 129 bins
#define TP     129                           // tile pitch (odd -> conflict-free cols)
#define SCR_N  8704                          // 32 groups * 272 (17-float pitch)
#define SMEM_FLOATS (2*TILE_N + 2*SCR_N)     // 201728 bytes
#define SMEM_BYTES (SMEM_FLOATS * 4)

// ---------------------------------------------------------------------------
template<int SGN>
__device__ __forceinline__ void fft4(float& r0, float& i0, float& r1, float& i1,
                                     float& r2, float& i2, float& r3, float& i3) {
    float t0r = r0 + r2, t0i = i0 + i2, t1r = r0 - r2, t1i = i0 - i2;
    float t2r = r1 + r3, t2i = i1 + i3, t3r = r1 - r3, t3i = i1 - i3;
    float w3r = (SGN < 0) ? t3i : -t3i;
    float w3i = (SGN < 0) ? -t3r : t3r;
    r0 = t0r + t2r; i0 = t0i + t2i;
    r2 = t0r - t2r; i2 = t0i - t2i;
    r1 = t1r + w3r; i1 = t1i + w3i;
    r3 = t1r - w3r; i3 = t1i - w3i;
}

// In-register 16-point DFT. PIN=false: natural input, X[k] lands at P16(k).
// PIN=true: input stored in P16 layout, output lands at P16(k) as well
// (register relabeling; P16 is an involution).
template<int SGN, bool PIN>
__device__ __forceinline__ void fft16(float* r, float* im) {
#define IXQ(n) (PIN ? ((((n) & 3) << 2) | (((n) >> 2) & 3)) : (n))
    #pragma unroll
    for (int b = 0; b < 4; b++)
        fft4<SGN>(r[IXQ(b)], im[IXQ(b)], r[IXQ(b+4)], im[IXQ(b+4)],
                  r[IXQ(b+8)], im[IXQ(b+8)], r[IXQ(b+12)], im[IXQ(b+12)]);
    const float TC[10] = {1.f, 0.92387953f, 0.70710678f, 0.38268343f, 0.f,
                          0.f, -0.70710678f, 0.f, 0.f, -0.92387953f};
    const float TS[10] = {0.f, 0.38268343f, 0.70710678f, 0.92387953f, 1.f,
                          0.f, 0.70710678f, 0.f, 0.f, -0.38268343f};
    #pragma unroll
    for (int k1 = 1; k1 < 4; k1++)
        #pragma unroll
        for (int b = 1; b < 4; b++) {
            const int m = k1 * b, p = IXQ(4*k1 + b);
            const float c = TC[m], s = (float)SGN * TS[m];
            float vr = r[p] * c - im[p] * s;
            im[p]    = r[p] * s + im[p] * c;
            r[p]     = vr;
        }
    #pragma unroll
    for (int k1 = 0; k1 < 4; k1++)
        fft4<SGN>(r[IXQ(4*k1)], im[IXQ(4*k1)], r[IXQ(4*k1+1)], im[IXQ(4*k1+1)],
                  r[IXQ(4*k1+2)], im[IXQ(4*k1+2)], r[IXQ(4*k1+3)], im[IXQ(4*k1+3)]);
#undef IXQ
}

// 256-pt FFT by one 16-thread group; dual scratch, one transpose pass.
// Thread j enters with z[16*n1+j] (natural if !PIN, P16 layout if PIN);
// exits with X[16*k2+j] at position P16(k2).
template<int SGN, bool PIN>
__device__ __forceinline__ void fft256_grp(float* zr, float* zi,
                                           float* sr, float* si, int j) {
    fft16<SGN, PIN>(zr, zi);
    float wjs, wjc;
    __sincosf((float)SGN * (6.2831853071795864f / 256.f) * (float)j, &wjs, &wjc);
    float wr = 1.f, wi = 0.f;
    __syncwarp();
    #pragma unroll
    for (int k1 = 0; k1 < 16; k1++) {
        const int p = PIN ? k1 : P16(k1);       // X[k1] position after fft16
        sr[k1 * 17 + j] = zr[p] * wr - zi[p] * wi;
        si[k1 * 17 + j] = zr[p] * wi + zi[p] * wr;
        float nr = wr * wjc - wi * wjs;
        wi = wr * wjs + wi * wjc; wr = nr;
    }
    __syncwarp();
    #pragma unroll
    for (int n2 = 0; n2 < 16; n2++) { zr[n2] = sr[j*17 + n2]; zi[n2] = si[j*17 + n2]; }
    fft16<SGN, false>(zr, zi);
}

// Unpack a packed-real forward FFT (Z of A+iB) into the two hermitian halves
// and write bins 0..128 of rows baseA/baseB into the tile.
__device__ __forceinline__ void unpack_rows_to_tile(
    const float* zr, const float* zi, float* tr, float* ti,
    int baseA, int baseB, int j) {
    #pragma unroll
    for (int k2 = 0; k2 < 8; k2++) {
        float sr_ = zr[P16(15 - k2)], si_ = zi[P16(15 - k2)];
        float mr_ = __shfl_sync(0xffffffffu, sr_, (16 - j) & 15, 16);
        float mi_ = __shfl_sync(0xffffffffu, si_, (16 - j) & 15, 16);
        if (j == 0) { mr_ = zr[P16((16 - k2) & 15)]; mi_ = zi[P16((16 - k2) & 15)]; }
        const float zkr = zr[P16(k2)], zki = zi[P16(k2)];
        tr[baseA + k2*16 + j] = 0.5f * (zkr + mr_);
        ti[baseA + k2*16 + j] = 0.5f * (zki - mi_);
        tr[baseB + k2*16 + j] = 0.5f * (zki + mi_);
        ti[baseB + k2*16 + j] = 0.5f * (mr_ - zkr);
    }
    if (j == 0) {                              // bin 128 (self-mirror, real)
        tr[baseA + 128] = zr[P16(8)];  ti[baseA + 128] = 0.f;
        tr[baseB + 128] = zi[P16(8)];  ti[baseB + 128] = 0.f;
    }
}

// ---------------------------------------------------------------------------
// kprep: one block per channel. MLP + packed row rFFTs -> tile, then column
// FFTs -> g_Kf (columns 0 and 128 packed as one complex FFT).
// ---------------------------------------------------------------------------
__global__ void __launch_bounds__(512)
kprep_kernel(const float* __restrict__ W1, const float* __restrict__ b1,
             const float* __restrict__ W2, const float* __restrict__ b2) {
    extern __shared__ float smem[];
    float* tr  = smem;
    float* ti  = smem + TILE_N;
    float* scr = smem + 2*TILE_N;
    const int t = threadIdx.x, g = t >> 4, j = t & 15;
    const int c = blockIdx.x;
    float* sr = scr + g * 272;
    float* si = scr + SCR_N + g * 272;

    float w1a[16], w1b[16], bb1[16], w2[16];
    #pragma unroll
    for (int h = 0; h < 16; h++) {
        w1a[h] = W1[h]; w1b[h] = W1[16 + h]; bb1[h] = b1[h]; w2[h] = W2[h * CH + c];
    }
    const float bias = b2[c];

    // Phase 1: 64 packed row FFTs (rows r, r+64), 2 iters
    #pragma unroll 1
    for (int it = 0; it < 2; it++) {
        const int rA = it * 32 + g, rB = rA + 64;
        const float gyA = (float)rA * (1.f / 127.f);
        const float gyB = (float)rB * (1.f / 127.f);
        float zr[16], zi[16];
        #pragma unroll
        for (int n1 = 0; n1 < 16; n1++) {
            const int col = n1 * 16 + j;
            float vA = 0.f, vB = 0.f;
            if (col < 128) {
                const float gx = (float)col * (1.f / 127.f);
                vA = bias; vB = bias;
                #pragma unroll
                for (int h = 0; h < 16; h++) {
                    const float gxw = gx * w1b[h] + bb1[h];
                    vA += fmaxf(gyA * w1a[h] + gxw, 0.f) * w2[h];
                    vB += fmaxf(gyB * w1a[h] + gxw, 0.f) * w2[h];
                }
            }
            zr[n1] = vA; zi[n1] = vB;
        }
        fft256_grp<-1, false>(zr, zi, sr, si, j);
        unpack_rows_to_tile(zr, zi, tr, ti, rA * TP, rB * TP, j);
    }
    __syncthreads();

    // Phase 2: 128 column tasks (task 0 = packed cols 0&128), 4 iters
    #pragma unroll 1
    for (int it = 0; it < 4; it++) {
        const int f = it * 32 + g;
        float zr[16], zi[16];
        #pragma unroll
        for (int n1 = 0; n1 < 8; n1++) {          // rows >= 128 are zero pad
            const int row = n1 * 16 + j;
            if (f == 0) { zr[n1] = tr[row * TP];     zi[n1] = tr[row * TP + 128]; }
            else        { zr[n1] = tr[row * TP + f]; zi[n1] = ti[row * TP + f]; }
        }
        #pragma unroll
        for (int n1 = 8; n1 < 16; n1++) { zr[n1] = 0.f; zi[n1] = 0.f; }
        fft256_grp<-1, false>(zr, zi, sr, si, j);

        if (f == 0) {
            // unpack hermitian spectra of cols 0 and 128, store Kf
            #pragma unroll
            for (int k2 = 0; k2 < 16; k2++) {
                const int p = P16(k2);
                float sr_ = zr[P16(15 - k2)], si_ = zi[P16(15 - k2)];
                float mr_ = __shfl_sync(0xffffu, sr_, (16 - j) & 15, 16);
                float mi_ = __shfl_sync(0xffffu, si_, (16 - j) & 15, 16);
                if (j == 0) { mr_ = zr[P16((16 - k2) & 15)]; mi_ = zi[P16((16 - k2) & 15)]; }
                const float Ar = 0.5f * (zr[p] + mr_), Ai = 0.5f * (zi[p] - mi_);
                const float Br = 0.5f * (zi[p] + mi_), Bi = 0.5f * (mr_ - zr[p]);
                g_Kf[(c * NF +   0) * 256 + k2*16 + j] = make_float2(Ar, Ai);
                g_Kf[(c * NF + 128) * 256 + k2*16 + j] = make_float2(Br, Bi);
            }
        } else {
            const int kb = (c * NF + f) * 256;
            #pragma unroll
            for (int k2 = 0; k2 < 16; k2++)
                g_Kf[kb + k2*16 + j] = make_float2(zr[P16(k2)], zi[P16(k2)]);
        }
    }
}

// ---------------------------------------------------------------------------
// Fused per-image kernel: 512 threads = 32 groups, one block per image.
// ---------------------------------------------------------------------------
__global__ void __launch_bounds__(512)
fused_kernel(const float* __restrict__ x, float* __restrict__ out) {
    extern __shared__ float smem[];
    float* tr  = smem;
    float* ti  = smem + TILE_N;
    float* scr = smem + 2*TILE_N;
    const int t = threadIdx.x, g = t >> 4, j = t & 15;
    const int bc = blockIdx.x;
    const int c  = bc % CH;
    float* sr = scr + g * 272;
    float* si = scr + SCR_N + g * 272;

    // ---- Phase 1: 64 packed row rFFTs (rows r, r+64), 2 iters ----
    #pragma unroll 1
    for (int it = 0; it < 2; it++) {
        const int rA = it * 32 + g, rB = rA + 64;
        const int xa = (bc * HH + rA) * WW;
        const int xb = (bc * HH + rB) * WW;
        float zr[16], zi[16];
        #pragma unroll
        for (int n1 = 0; n1 < 16; n1++) {
            const int col = n1 * 16 + j;
            if (col < 128) { zr[n1] = x[xa + col]; zi[n1] = x[xb + col]; }
            else           { zr[n1] = 0.f;         zi[n1] = 0.f; }
        }
        fft256_grp<-1, false>(zr, zi, sr, si, j);
        unpack_rows_to_tile(zr, zi, tr, ti, rA * TP, rB * TP, j);
    }
    __syncthreads();

    // ---- Phase 2: 128 column tasks (task 0 = packed cols 0&128), 4 iters ----
    #pragma unroll 1
    for (int it = 0; it < 4; it++) {
        const int f = it * 32 + g;
        float zr[16], zi[16];
        #pragma unroll
        for (int n1 = 0; n1 < 8; n1++) {          // rows >= 128 are zero pad
            const int row = n1 * 16 + j;
            if (f == 0) { zr[n1] = tr[row * TP];     zi[n1] = tr[row * TP + 128]; }
            else        { zr[n1] = tr[row * TP + f]; zi[n1] = ti[row * TP + f]; }
        }
        #pragma unroll
        for (int n1 = 8; n1 < 16; n1++) { zr[n1] = 0.f; zi[n1] = 0.f; }
        fft256_grp<-1, false>(zr, zi, sr, si, j);  // forward along column

        if (f == 0) {
            float or_[16], oi_[16];                // snapshot (mirror needs pre-mult)
            #pragma unroll
            for (int q = 0; q < 16; q++) { or_[q] = zr[q]; oi_[q] = zi[q]; }
            #pragma unroll
            for (int k2 = 0; k2 < 16; k2++) {
                const int p = P16(k2);
                float mr_ = __shfl_sync(0xffffu, or_[P16(15 - k2)], (16 - j) & 15, 16);
                float mi_ = __shfl_sync(0xffffu, oi_[P16(15 - k2)], (16 - j) & 15, 16);
                if (j == 0) { mr_ = or_[P16((16 - k2) & 15)]; mi_ = oi_[P16((16 - k2) & 15)]; }
                const float Ar = 0.5f * (or_[p] + mr_), Ai = 0.5f * (oi_[p] - mi_);
                const float Br = 0.5f * (oi_[p] + mi_), Bi = 0.5f * (mr_ - or_[p]);
                const float2 k0 = g_Kf[(c * NF +   0) * 256 + k2*16 + j];
                const float2 kn = g_Kf[(c * NF + 128) * 256 + k2*16 + j];
                const float Cr = Ar * k0.x - Ai * k0.y, Ci = Ar * k0.y + Ai * k0.x;
                const float Dr = Br * kn.x - Bi * kn.y, Di = Br * kn.y + Bi * kn.x;
                zr[p] = Cr - Di;                   // repack: Y = C + i*D
                zi[p] = Ci + Dr;
            }
        } else {
            const int kb = (c * NF + f) * 256;
            #pragma unroll
            for (int k2 = 0; k2 < 16; k2++) {
                const float2 kv = g_Kf[kb + k2*16 + j];
                const int p = P16(k2);
                const float a = zr[p], b = zi[p];
                zr[p] = a * kv.x - b * kv.y;
                zi[p] = a * kv.y + b * kv.x;
            }
        }
        fft256_grp<1, true>(zr, zi, sr, si, j);    // unnormalized inverse (PIN)
        if (f == 0) {
            #pragma unroll
            for (int k2 = 0; k2 < 8; k2++) {       // keep rows 0..127; cols real
                const int row = k2 * 16 + j;
                tr[row * TP]       = zr[P16(k2)];  ti[row * TP]       = 0.f;
                tr[row * TP + 128] = zi[P16(k2)];  ti[row * TP + 128] = 0.f;
            }
        } else {
            #pragma unroll
            for (int k2 = 0; k2 < 8; k2++) {
                const int row = k2 * 16 + j;
                tr[row * TP + f] = zr[P16(k2)];
                ti[row * TP + f] = zi[P16(k2)];
            }
        }
    }
    __syncthreads();

    // ---- Phase 3: 64 packed hermitian row inverses + residual, 2 iters ----
    #pragma unroll 1
    for (int it = 0; it < 2; it++) {
        const int rA = it * 32 + g, rB = rA + 64;
        const int baseA = rA * TP, baseB = rB * TP;
        float zr[16], zi[16];
        #pragma unroll
        for (int n1 = 0; n1 < 16; n1++) {
            const int n = n1 * 16 + j;
            float Ar, Ai, Br, Bi;
            if (n <= 128) {
                Ar = tr[baseA + n]; Ai = ti[baseA + n];
                Br = tr[baseB + n]; Bi = ti[baseB + n];
            } else {
                const int m2 = 256 - n;            // hermitian mirror
                Ar = tr[baseA + m2]; Ai = -ti[baseA + m2];
                Br = tr[baseB + m2]; Bi = -ti[baseB + m2];
            }
            zr[n1] = Ar - Bi;                      // Z = A + i*B
            zi[n1] = Ai + Br;
        }
        fft256_grp<1, false>(zr, zi, sr, si, j);   // z[n] = a[n] + i*b[n]
        const int ga = (bc * HH + rA) * WW;
        const int gb = (bc * HH + rB) * WW;
        #pragma unroll
        for (int k2 = 0; k2 < 8; k2++) {
            const int col = k2 * 16 + j;
            out[ga + col] = zr[P16(k2)] + x[ga + col];
            out[gb + col] = zi[P16(k2)] + x[gb + col];
        }
    }
}

// ---------------------------------------------------------------------------
extern "C" void kernel_launch(void* const* d_in, const int* in_sizes, int n_in,
                              void* d_out, int out_size) {
    const float* x  = (const float*)d_in[0];
    const float* W1 = (const float*)d_in[1];
    const float* b1 = (const float*)d_in[2];
    const float* W2 = (const float*)d_in[3];
    const float* b2 = (const float*)d_in[4];
    float* out = (float*)d_out;

    static int smem_set = 0;
    if (!smem_set) {
        cudaFuncSetAttribute(kprep_kernel,
                             cudaFuncAttributeMaxDynamicSharedMemorySize, SMEM_BYTES);
        cudaFuncSetAttribute(fused_kernel,
                             cudaFuncAttributeMaxDynamicSharedMemorySize, SMEM_BYTES);
        smem_set = 1;
    }

    kprep_kernel<<<CH, 512, SMEM_BYTES>>>(W1, b1, W2, b2);
    fused_kernel<<<BC, 512, SMEM_BYTES>>>(x, out);
}

// round 13
// speedup vs baseline: 1.3469x; 1.1087x over previous
#include <cuda_runtime.h>
#include <cuda_bf16.h>

#define CH 96
#define HH 128
#define WW 128
#define BC 1536
#define NF 129

// digit-reversed base-4 position (involution: P16(P16(k)) == k)
#define P16(k) ((((k) & 3) << 2) | ((k) >> 2))

__device__ float2 g_Kf[CH * NF * 256];       // full 2D FFT of k  [c][f][m]

#define TILE_N 16512                         // 128 rows * 129 bins (float2)
#define TP     129                           // tile pitch in float2 (odd -> conflict-free)
#define SCR_N  8704                          // 32 groups * 272 float2 (17-f2 pitch)
#define SMEM_BYTES ((TILE_N + SCR_N) * 8)    // 201728 B

// ---------------------------------------------------------------------------
template<int SGN>
__device__ __forceinline__ void fft4(float& r0, float& i0, float& r1, float& i1,
                                     float& r2, float& i2, float& r3, float& i3) {
    float t0r = r0 + r2, t0i = i0 + i2, t1r = r0 - r2, t1i = i0 - i2;
    float t2r = r1 + r3, t2i = i1 + i3, t3r = r1 - r3, t3i = i1 - i3;
    float w3r = (SGN < 0) ? t3i : -t3i;
    float w3i = (SGN < 0) ? -t3r : t3r;
    r0 = t0r + t2r; i0 = t0i + t2i;
    r2 = t0r - t2r; i2 = t0i - t2i;
    r1 = t1r + w3r; i1 = t1i + w3i;
    r3 = t1r - w3r; i3 = t1i - w3i;
}

// In-register 16-point DFT. PIN=false: natural input, X[k] lands at P16(k).
// PIN=true: input stored in P16 layout (register relabeling; P16 involution).
template<int SGN, bool PIN>
__device__ __forceinline__ void fft16(float* r, float* im) {
#define IXQ(n) (PIN ? ((((n) & 3) << 2) | (((n) >> 2) & 3)) : (n))
    #pragma unroll
    for (int b = 0; b < 4; b++)
        fft4<SGN>(r[IXQ(b)], im[IXQ(b)], r[IXQ(b+4)], im[IXQ(b+4)],
                  r[IXQ(b+8)], im[IXQ(b+8)], r[IXQ(b+12)], im[IXQ(b+12)]);
    const float TC[10] = {1.f, 0.92387953f, 0.70710678f, 0.38268343f, 0.f,
                          0.f, -0.70710678f, 0.f, 0.f, -0.92387953f};
    const float TS[10] = {0.f, 0.38268343f, 0.70710678f, 0.92387953f, 1.f,
                          0.f, 0.70710678f, 0.f, 0.f, -0.38268343f};
    #pragma unroll
    for (int k1 = 1; k1 < 4; k1++)
        #pragma unroll
        for (int b = 1; b < 4; b++) {
            const int m = k1 * b, p = IXQ(4*k1 + b);
            const float c = TC[m], s = (float)SGN * TS[m];
            float vr = r[p] * c - im[p] * s;
            im[p]    = r[p] * s + im[p] * c;
            r[p]     = vr;
        }
    #pragma unroll
    for (int k1 = 0; k1 < 4; k1++)
        fft4<SGN>(r[IXQ(4*k1)], im[IXQ(4*k1)], r[IXQ(4*k1+1)], im[IXQ(4*k1+1)],
                  r[IXQ(4*k1+2)], im[IXQ(4*k1+2)], r[IXQ(4*k1+3)], im[IXQ(4*k1+3)]);
#undef IXQ
}

// 256-pt FFT by one 16-thread group; float2 scratch, pitch-17, one pass.
// Thread j enters with z[16*n1+j] (natural if !PIN, P16 layout if PIN);
// exits with X[16*k2+j] at position P16(k2).
template<int SGN, bool PIN>
__device__ __forceinline__ void fft256_grp(float* zr, float* zi,
                                           float2* sc, int j) {
    fft16<SGN, PIN>(zr, zi);
    float wjs, wjc;
    __sincosf((float)SGN * (6.2831853071795864f / 256.f) * (float)j, &wjs, &wjc);
    float wr = 1.f, wi = 0.f;
    __syncwarp();
    #pragma unroll
    for (int k1 = 0; k1 < 16; k1++) {
        const int p = PIN ? k1 : P16(k1);       // X[k1] position after fft16
        sc[k1 * 17 + j] = make_float2(zr[p] * wr - zi[p] * wi,
                                      zr[p] * wi + zi[p] * wr);
        float nr = wr * wjc - wi * wjs;
        wi = wr * wjs + wi * wjc; wr = nr;
    }
    __syncwarp();
    #pragma unroll
    for (int n2 = 0; n2 < 16; n2++) {
        const float2 v = sc[j * 17 + n2];
        zr[n2] = v.x; zi[n2] = v.y;
    }
    fft16<SGN, false>(zr, zi);
}

// Unpack a packed-real forward FFT (Z of A+iB) into the two hermitian halves
// and write bins 0..128 of rows baseA/baseB into the float2 tile.
__device__ __forceinline__ void unpack_rows_to_tile(
    const float* zr, const float* zi, float2* tile, int baseA, int baseB, int j) {
    #pragma unroll
    for (int k2 = 0; k2 < 8; k2++) {
        float sr_ = zr[P16(15 - k2)], si_ = zi[P16(15 - k2)];
        float mr_ = __shfl_sync(0xffffffffu, sr_, (16 - j) & 15, 16);
        float mi_ = __shfl_sync(0xffffffffu, si_, (16 - j) & 15, 16);
        if (j == 0) { mr_ = zr[P16((16 - k2) & 15)]; mi_ = zi[P16((16 - k2) & 15)]; }
        const float zkr = zr[P16(k2)], zki = zi[P16(k2)];
        tile[baseA + k2*16 + j] = make_float2(0.5f * (zkr + mr_), 0.5f * (zki - mi_));
        tile[baseB + k2*16 + j] = make_float2(0.5f * (zki + mi_), 0.5f * (mr_ - zkr));
    }
    if (j == 0) {                              // bin 128 (self-mirror, real)
        tile[baseA + 128] = make_float2(zr[P16(8)], 0.f);
        tile[baseB + 128] = make_float2(zi[P16(8)], 0.f);
    }
}

// ---------------------------------------------------------------------------
// kprep: one block per channel. MLP + packed row rFFTs -> tile, then column
// FFTs -> g_Kf (columns 0 and 128 packed as one complex FFT).
// ---------------------------------------------------------------------------
__global__ void __launch_bounds__(512)
kprep_kernel(const float* __restrict__ W1, const float* __restrict__ b1,
             const float* __restrict__ W2, const float* __restrict__ b2) {
    extern __shared__ float2 smem2[];
    float2* tile = smem2;
    float2* sc   = smem2 + TILE_N + (threadIdx.x >> 4) * 272;
    const int t = threadIdx.x, g = t >> 4, j = t & 15;
    const int c = blockIdx.x;

    float w1a[16], w1b[16], bb1[16], w2[16];
    #pragma unroll
    for (int h = 0; h < 16; h++) {
        w1a[h] = W1[h]; w1b[h] = W1[16 + h]; bb1[h] = b1[h]; w2[h] = W2[h * CH + c];
    }
    const float bias = b2[c];

    // Phase 1: 64 packed row FFTs (rows r, r+64), 2 iters
    #pragma unroll 1
    for (int it = 0; it < 2; it++) {
        const int rA = it * 32 + g, rB = rA + 64;
        const float gyA = (float)rA * (1.f / 127.f);
        const float gyB = (float)rB * (1.f / 127.f);
        float zr[16], zi[16];
        #pragma unroll
        for (int n1 = 0; n1 < 16; n1++) {
            const int col = n1 * 16 + j;
            float vA = 0.f, vB = 0.f;
            if (col < 128) {
                const float gx = (float)col * (1.f / 127.f);
                vA = bias; vB = bias;
                #pragma unroll
                for (int h = 0; h < 16; h++) {
                    const float gxw = gx * w1b[h] + bb1[h];
                    vA += fmaxf(gyA * w1a[h] + gxw, 0.f) * w2[h];
                    vB += fmaxf(gyB * w1a[h] + gxw, 0.f) * w2[h];
                }
            }
            zr[n1] = vA; zi[n1] = vB;
        }
        fft256_grp<-1, false>(zr, zi, sc, j);
        unpack_rows_to_tile(zr, zi, tile, rA * TP, rB * TP, j);
    }
    __syncthreads();

    // Phase 2: 128 column tasks (task 0 = packed cols 0&128), 4 iters
    #pragma unroll 1
    for (int it = 0; it < 4; it++) {
        const int f = it * 32 + g;
        float zr[16], zi[16];
        #pragma unroll
        for (int n1 = 0; n1 < 8; n1++) {          // rows >= 128 are zero pad
            const int row = n1 * 16 + j;
            if (f == 0) { zr[n1] = tile[row * TP].x; zi[n1] = tile[row * TP + 128].x; }
            else        { const float2 v = tile[row * TP + f]; zr[n1] = v.x; zi[n1] = v.y; }
        }
        #pragma unroll
        for (int n1 = 8; n1 < 16; n1++) { zr[n1] = 0.f; zi[n1] = 0.f; }
        fft256_grp<-1, false>(zr, zi, sc, j);

        if (f == 0) {
            // unpack hermitian spectra of cols 0 and 128, store Kf
            #pragma unroll
            for (int k2 = 0; k2 < 16; k2++) {
                const int p = P16(k2);
                float sr_ = zr[P16(15 - k2)], si_ = zi[P16(15 - k2)];
                float mr_ = __shfl_sync(0xffffu, sr_, (16 - j) & 15, 16);
                float mi_ = __shfl_sync(0xffffu, si_, (16 - j) & 15, 16);
                if (j == 0) { mr_ = zr[P16((16 - k2) & 15)]; mi_ = zi[P16((16 - k2) & 15)]; }
                const float Ar = 0.5f * (zr[p] + mr_), Ai = 0.5f * (zi[p] - mi_);
                const float Br = 0.5f * (zi[p] + mi_), Bi = 0.5f * (mr_ - zr[p]);
                g_Kf[(c * NF +   0) * 256 + k2*16 + j] = make_float2(Ar, Ai);
                g_Kf[(c * NF + 128) * 256 + k2*16 + j] = make_float2(Br, Bi);
            }
        } else {
            const int kb = (c * NF + f) * 256;
            #pragma unroll
            for (int k2 = 0; k2 < 16; k2++)
                g_Kf[kb + k2*16 + j] = make_float2(zr[P16(k2)], zi[P16(k2)]);
        }
    }
}

// ---------------------------------------------------------------------------
// Fused per-image kernel: 512 threads = 32 groups, one block per image.
// ---------------------------------------------------------------------------
__global__ void __launch_bounds__(512)
fused_kernel(const float* __restrict__ x, float* __restrict__ out) {
    extern __shared__ float2 smem2[];
    float2* tile = smem2;
    float2* sc   = smem2 + TILE_N + (threadIdx.x >> 4) * 272;
    const int t = threadIdx.x, g = t >> 4, j = t & 15;
    const int bc = blockIdx.x;
    const int c  = bc % CH;

    // ---- Phase 1: 64 packed row rFFTs (rows r, r+64), 2 iters ----
    #pragma unroll 1
    for (int it = 0; it < 2; it++) {
        const int rA = it * 32 + g, rB = rA + 64;
        const int xa = (bc * HH + rA) * WW;
        const int xb = (bc * HH + rB) * WW;
        float zr[16], zi[16];
        #pragma unroll
        for (int n1 = 0; n1 < 16; n1++) {
            const int col = n1 * 16 + j;
            if (col < 128) { zr[n1] = x[xa + col]; zi[n1] = x[xb + col]; }
            else           { zr[n1] = 0.f;         zi[n1] = 0.f; }
        }
        fft256_grp<-1, false>(zr, zi, sc, j);
        unpack_rows_to_tile(zr, zi, tile, rA * TP, rB * TP, j);
    }
    __syncthreads();

    // ---- Phase 2: 128 column tasks (task 0 = packed cols 0&128), 4 iters ----
    #pragma unroll 1
    for (int it = 0; it < 4; it++) {
        const int f = it * 32 + g;
        float zr[16], zi[16];
        #pragma unroll
        for (int n1 = 0; n1 < 8; n1++) {          // rows >= 128 are zero pad
            const int row = n1 * 16 + j;
            if (f == 0) { zr[n1] = tile[row * TP].x; zi[n1] = tile[row * TP + 128].x; }
            else        { const float2 v = tile[row * TP + f]; zr[n1] = v.x; zi[n1] = v.y; }
        }
        #pragma unroll
        for (int n1 = 8; n1 < 16; n1++) { zr[n1] = 0.f; zi[n1] = 0.f; }
        fft256_grp<-1, false>(zr, zi, sc, j);      // forward along column

        if (f == 0) {
            float or_[16], oi_[16];                // snapshot (mirror needs pre-mult)
            #pragma unroll
            for (int q = 0; q < 16; q++) { or_[q] = zr[q]; oi_[q] = zi[q]; }
            #pragma unroll
            for (int k2 = 0; k2 < 16; k2++) {
                const int p = P16(k2);
                float mr_ = __shfl_sync(0xffffu, or_[P16(15 - k2)], (16 - j) & 15, 16);
                float mi_ = __shfl_sync(0xffffu, oi_[P16(15 - k2)], (16 - j) & 15, 16);
                if (j == 0) { mr_ = or_[P16((16 - k2) & 15)]; mi_ = oi_[P16((16 - k2) & 15)]; }
                const float Ar = 0.5f * (or_[p] + mr_), Ai = 0.5f * (oi_[p] - mi_);
                const float Br = 0.5f * (oi_[p] + mi_), Bi = 0.5f * (mr_ - or_[p]);
                const float2 k0 = g_Kf[(c * NF +   0) * 256 + k2*16 + j];
                const float2 kn = g_Kf[(c * NF + 128) * 256 + k2*16 + j];
                const float Cr = Ar * k0.x - Ai * k0.y, Ci = Ar * k0.y + Ai * k0.x;
                const float Dr = Br * kn.x - Bi * kn.y, Di = Br * kn.y + Bi * kn.x;
                zr[p] = Cr - Di;                   // repack: Y = C + i*D
                zi[p] = Ci + Dr;
            }
        } else {
            const int kb = (c * NF + f) * 256;
            #pragma unroll
            for (int k2 = 0; k2 < 16; k2++) {
                const float2 kv = g_Kf[kb + k2*16 + j];
                const int p = P16(k2);
                const float a = zr[p], b = zi[p];
                zr[p] = a * kv.x - b * kv.y;
                zi[p] = a * kv.y + b * kv.x;
            }
        }
        fft256_grp<1, true>(zr, zi, sc, j);        // unnormalized inverse (PIN)
        if (f == 0) {
            #pragma unroll
            for (int k2 = 0; k2 < 8; k2++) {       // keep rows 0..127; cols real
                const int row = k2 * 16 + j;
                tile[row * TP]       = make_float2(zr[P16(k2)], 0.f);
                tile[row * TP + 128] = make_float2(zi[P16(k2)], 0.f);
            }
        } else {
            #pragma unroll
            for (int k2 = 0; k2 < 8; k2++) {
                const int row = k2 * 16 + j;
                tile[row * TP + f] = make_float2(zr[P16(k2)], zi[P16(k2)]);
            }
        }
    }
    __syncthreads();

    // ---- Phase 3: 64 packed hermitian row inverses + residual, 2 iters ----
    #pragma unroll 1
    for (int it = 0; it < 2; it++) {
        const int rA = it * 32 + g, rB = rA + 64;
        const int baseA = rA * TP, baseB = rB * TP;
        float zr[16], zi[16];
        #pragma unroll
        for (int n1 = 0; n1 < 16; n1++) {
            const int n = n1 * 16 + j;
            float Ar, Ai, Br, Bi;
            if (n <= 128) {
                const float2 vA = tile[baseA + n], vB = tile[baseB + n];
                Ar = vA.x; Ai = vA.y; Br = vB.x; Bi = vB.y;
            } else {
                const int m2 = 256 - n;            // hermitian mirror
                const float2 vA = tile[baseA + m2], vB = tile[baseB + m2];
                Ar = vA.x; Ai = -vA.y; Br = vB.x; Bi = -vB.y;
            }
            zr[n1] = Ar - Bi;                      // Z = A + i*B
            zi[n1] = Ai + Br;
        }
        fft256_grp<1, false>(zr, zi, sc, j);       // z[n] = a[n] + i*b[n]
        const int ga = (bc * HH + rA) * WW;
        const int gb = (bc * HH + rB) * WW;
        #pragma unroll
        for (int k2 = 0; k2 < 8; k2++) {
            const int col = k2 * 16 + j;
            out[ga + col] = zr[P16(k2)] + x[ga + col];
            out[gb + col] = zi[P16(k2)] + x[gb + col];
        }
    }
}

// ---------------------------------------------------------------------------
extern "C" void kernel_launch(void* const* d_in, const int* in_sizes, int n_in,
                              void* d_out, int out_size) {
    const float* x  = (const float*)d_in[0];
    const float* W1 = (const float*)d_in[1];
    const float* b1 = (const float*)d_in[2];
    const float* W2 = (const float*)d_in[3];
    const float* b2 = (const float*)d_in[4];
    float* out = (float*)d_out;

    static int smem_set = 0;
    if (!smem_set) {
        cudaFuncSetAttribute(kprep_kernel,
                             cudaFuncAttributeMaxDynamicSharedMemorySize, SMEM_BYTES);
        cudaFuncSetAttribute(fused_kernel,
                             cudaFuncAttributeMaxDynamicSharedMemorySize, SMEM_BYTES);
        smem_set = 1;
    }

    kprep_kernel<<<CH, 512, SMEM_BYTES>>>(W1, b1, W2, b2);
    fused_kernel<<<BC, 512, SMEM_BYTES>>>(x, out);
}

// round 16
// speedup vs baseline: 1.3956x; 1.0361x over previous
#include <cuda_runtime.h>
#include <cuda_bf16.h>

#define CH 96
#define HH 128
#define WW 128
#define BC 1536
#define NF 129

// digit-reversed base-4 position (involution: P16(P16(k)) == k)
#define P16(k) ((((k) & 3) << 2) | ((k) >> 2))

__device__ float2 g_Kf[CH * NF * 256];       // full 2D FFT of k  [c][f][m]

#define TILE_N 16512                         // 128 rows * 129 bins (float2)
#define TP     129                           // tile pitch in float2 (odd -> conflict-free)
#define SCR_N  8704                          // 32 groups * 272 float2 (17-f2 pitch)
#define SMEM_BYTES ((TILE_N + SCR_N) * 8)    // 201728 B

// ---------------------------------------------------------------------------
// Packed f32x2 helpers (one instruction = two float ops; ptxas never emits
// these from C++ — PTX-only pattern).
__device__ __forceinline__ float2 f2add(float2 a, float2 b) {
    union { float2 f; unsigned long long u; } A, B, R;
    A.f = a; B.f = b;
    asm("add.rn.f32x2 %0, %1, %2;" : "=l"(R.u) : "l"(A.u), "l"(B.u));
    return R.f;
}
__device__ __forceinline__ float2 f2sub(float2 a, float2 b) {
    union { float2 f; unsigned long long u; } A, B, R;
    A.f = a; B.f = b;
    asm("sub.rn.f32x2 %0, %1, %2;" : "=l"(R.u) : "l"(A.u), "l"(B.u));
    return R.f;
}

// Full 4-pt butterfly on packed complex values (in place).
template<int SGN>
__device__ __forceinline__ void fft4p(float2& a0, float2& a1, float2& a2, float2& a3) {
    float2 t0 = f2add(a0, a2), t1 = f2sub(a0, a2);
    float2 t2 = f2add(a1, a3), t3 = f2sub(a1, a3);
    a0 = f2add(t0, t2); a2 = f2sub(t0, t2);
    const float2 w3 = (SGN < 0) ? make_float2(t3.y, -t3.x) : make_float2(-t3.y, t3.x);
    a1 = f2add(t1, w3); a3 = f2sub(t1, w3);
}

// Degenerate 4-pt butterfly: inputs a2 = a3 = 0 (only a0, a1 read).
template<int SGN>
__device__ __forceinline__ void fft4h(float2& a0, float2& a1, float2& a2, float2& a3) {
    const float2 s = f2add(a0, a1), d = f2sub(a0, a1);
    const float2 w = (SGN < 0) ? make_float2(a1.y, -a1.x) : make_float2(-a1.y, a1.x);
    const float2 o1 = f2add(a0, w), o3 = f2sub(a0, w);
    a0 = s; a2 = d; a1 = o1; a3 = o3;
}

// In-register 16-point DFT on float2[16]. PIN=false: natural input, X[k] at
// P16(k). PIN=true: input in P16 layout (register relabeling). HALF: input
// slots 8..15 (natural indexing) are zero and never read.
template<int SGN, bool PIN, bool HALF>
__device__ __forceinline__ void fft16p(float2* z) {
#define IXQ(n) (PIN ? ((((n) & 3) << 2) | (((n) >> 2) & 3)) : (n))
    #pragma unroll
    for (int b = 0; b < 4; b++) {
        if (HALF) fft4h<SGN>(z[IXQ(b)], z[IXQ(b+4)], z[IXQ(b+8)], z[IXQ(b+12)]);
        else      fft4p<SGN>(z[IXQ(b)], z[IXQ(b+4)], z[IXQ(b+8)], z[IXQ(b+12)]);
    }
    const float TC[10] = {1.f, 0.92387953f, 0.70710678f, 0.38268343f, 0.f,
                          0.f, -0.70710678f, 0.f, 0.f, -0.92387953f};
    const float TS[10] = {0.f, 0.38268343f, 0.70710678f, 0.92387953f, 1.f,
                          0.f, 0.70710678f, 0.f, 0.f, -0.38268343f};
    #pragma unroll
    for (int k1 = 1; k1 < 4; k1++)
        #pragma unroll
        for (int b = 1; b < 4; b++) {
            const int m = k1 * b, p = IXQ(4*k1 + b);
            const float c = TC[m], s = (float)SGN * TS[m];
            const float vr = z[p].x * c - z[p].y * s;
            z[p].y = z[p].x * s + z[p].y * c;
            z[p].x = vr;
        }
    #pragma unroll
    for (int k1 = 0; k1 < 4; k1++)
        fft4p<SGN>(z[IXQ(4*k1)], z[IXQ(4*k1+1)], z[IXQ(4*k1+2)], z[IXQ(4*k1+3)]);
#undef IXQ
}

// 256-pt FFT by one 16-thread group; float2 scratch, pitch-17, one pass.
// Thread j enters with z[16*n1+j] (natural if !PIN, P16 layout if PIN);
// exits with X[16*k2+j] at position P16(k2).
template<int SGN, bool PIN, bool HALF>
__device__ __forceinline__ void fft256_grp(float2* z, float2* sc, int j) {
    fft16p<SGN, PIN, HALF>(z);
    float wjs, wjc;
    __sincosf((float)SGN * (6.2831853071795864f / 256.f) * (float)j, &wjs, &wjc);
    float wr = 1.f, wi = 0.f;
    __syncwarp();
    #pragma unroll
    for (int k1 = 0; k1 < 16; k1++) {
        const int p = PIN ? k1 : P16(k1);       // X[k1] position after fft16
        sc[k1 * 17 + j] = make_float2(z[p].x * wr - z[p].y * wi,
                                      z[p].x * wi + z[p].y * wr);
        const float nr = wr * wjc - wi * wjs;
        wi = wr * wjs + wi * wjc; wr = nr;
    }
    __syncwarp();
    #pragma unroll
    for (int n2 = 0; n2 < 16; n2++) z[n2] = sc[j * 17 + n2];
    fft16p<SGN, false, false>(z);
}

// Unpack a packed-real forward FFT (Z of A+iB) into the two hermitian halves
// and write bins 0..128 of rows baseA/baseB into the float2 tile.
__device__ __forceinline__ void unpack_rows_to_tile(
    const float2* z, float2* tile, int baseA, int baseB, int j) {
    #pragma unroll
    for (int k2 = 0; k2 < 8; k2++) {
        const float2 zm = z[P16(15 - k2)];
        float mr_ = __shfl_sync(0xffffffffu, zm.x, (16 - j) & 15, 16);
        float mi_ = __shfl_sync(0xffffffffu, zm.y, (16 - j) & 15, 16);
        if (j == 0) { const float2 z0 = z[P16((16 - k2) & 15)]; mr_ = z0.x; mi_ = z0.y; }
        const float2 zk = z[P16(k2)];
        tile[baseA + k2*16 + j] = make_float2(0.5f * (zk.x + mr_), 0.5f * (zk.y - mi_));
        tile[baseB + k2*16 + j] = make_float2(0.5f * (zk.y + mi_), 0.5f * (mr_ - zk.x));
    }
    if (j == 0) {                              // bin 128 (self-mirror, real)
        tile[baseA + 128] = make_float2(z[P16(8)].x, 0.f);
        tile[baseB + 128] = make_float2(z[P16(8)].y, 0.f);
    }
}

// ---------------------------------------------------------------------------
// kprep: one block per channel. MLP + packed row rFFTs -> tile, then column
// FFTs -> g_Kf (columns 0 and 128 packed as one complex FFT).
// ---------------------------------------------------------------------------
__global__ void __launch_bounds__(512)
kprep_kernel(const float* __restrict__ W1, const float* __restrict__ b1,
             const float* __restrict__ W2, const float* __restrict__ b2) {
    extern __shared__ float2 smem2[];
    float2* tile = smem2;
    float2* sc   = smem2 + TILE_N + (threadIdx.x >> 4) * 272;
    const int t = threadIdx.x, g = t >> 4, j = t & 15;
    const int c = blockIdx.x;

    float w1a[16], w1b[16], bb1[16], w2[16];
    #pragma unroll
    for (int h = 0; h < 16; h++) {
        w1a[h] = W1[h]; w1b[h] = W1[16 + h]; bb1[h] = b1[h]; w2[h] = W2[h * CH + c];
    }
    const float bias = b2[c];

    // Phase 1: 64 packed row FFTs (rows r, r+64), 2 iters  (HALF: cols<128)
    #pragma unroll 1
    for (int it = 0; it < 2; it++) {
        const int rA = it * 32 + g, rB = rA + 64;
        const float gyA = (float)rA * (1.f / 127.f);
        const float gyB = (float)rB * (1.f / 127.f);
        float2 z[16];
        #pragma unroll
        for (int n1 = 0; n1 < 8; n1++) {
            const int col = n1 * 16 + j;          // always < 128
            const float gx = (float)col * (1.f / 127.f);
            float vA = bias, vB = bias;
            #pragma unroll
            for (int h = 0; h < 16; h++) {
                const float gxw = gx * w1b[h] + bb1[h];
                vA += fmaxf(gyA * w1a[h] + gxw, 0.f) * w2[h];
                vB += fmaxf(gyB * w1a[h] + gxw, 0.f) * w2[h];
            }
            z[n1] = make_float2(vA, vB);
        }
        fft256_grp<-1, false, true>(z, sc, j);
        unpack_rows_to_tile(z, tile, rA * TP, rB * TP, j);
    }
    __syncthreads();

    // Phase 2: 128 column tasks (task 0 = packed cols 0&128), 4 iters (HALF)
    #pragma unroll 1
    for (int it = 0; it < 4; it++) {
        const int f = it * 32 + g;
        float2 z[16];
        #pragma unroll
        for (int n1 = 0; n1 < 8; n1++) {          // rows >= 128 are zero pad
            const int row = n1 * 16 + j;
            if (f == 0) z[n1] = make_float2(tile[row * TP].x, tile[row * TP + 128].x);
            else        z[n1] = tile[row * TP + f];
        }
        fft256_grp<-1, false, true>(z, sc, j);

        if (f == 0) {
            // unpack hermitian spectra of cols 0 and 128, store Kf
            #pragma unroll
            for (int k2 = 0; k2 < 16; k2++) {
                const int p = P16(k2);
                const float2 zm = z[P16(15 - k2)];
                float mr_ = __shfl_sync(0xffffu, zm.x, (16 - j) & 15, 16);
                float mi_ = __shfl_sync(0xffffu, zm.y, (16 - j) & 15, 16);
                if (j == 0) { const float2 z0 = z[P16((16 - k2) & 15)]; mr_ = z0.x; mi_ = z0.y; }
                const float Ar = 0.5f * (z[p].x + mr_), Ai = 0.5f * (z[p].y - mi_);
                const float Br = 0.5f * (z[p].y + mi_), Bi = 0.5f * (mr_ - z[p].x);
                g_Kf[(c * NF +   0) * 256 + k2*16 + j] = make_float2(Ar, Ai);
                g_Kf[(c * NF + 128) * 256 + k2*16 + j] = make_float2(Br, Bi);
            }
        } else {
            const int kb = (c * NF + f) * 256;
            #pragma unroll
            for (int k2 = 0; k2 < 16; k2++)
                g_Kf[kb + k2*16 + j] = z[P16(k2)];
        }
    }
}

// ---------------------------------------------------------------------------
// Fused per-image kernel: 512 threads = 32 groups, one block per image.
// ---------------------------------------------------------------------------
__global__ void __launch_bounds__(512)
fused_kernel(const float* __restrict__ x, float* __restrict__ out) {
    extern __shared__ float2 smem2[];
    float2* tile = smem2;
    float2* sc   = smem2 + TILE_N + (threadIdx.x >> 4) * 272;
    const int t = threadIdx.x, g = t >> 4, j = t & 15;
    const int bc = blockIdx.x;
    const int c  = bc % CH;

    // ---- Phase 1: 64 packed row rFFTs (rows r, r+64), 2 iters (HALF) ----
    #pragma unroll 1
    for (int it = 0; it < 2; it++) {
        const int rA = it * 32 + g, rB = rA + 64;
        const int xa = (bc * HH + rA) * WW;
        const int xb = (bc * HH + rB) * WW;
        float2 z[16];
        #pragma unroll
        for (int n1 = 0; n1 < 8; n1++) {
            const int col = n1 * 16 + j;          // always < 128
            z[n1] = make_float2(x[xa + col], x[xb + col]);
        }
        fft256_grp<-1, false, true>(z, sc, j);
        unpack_rows_to_tile(z, tile, rA * TP, rB * TP, j);
    }
    __syncthreads();

    // ---- Phase 2: 128 column tasks (task 0 = packed cols 0&128), 4 iters ----
    #pragma unroll 1
    for (int it = 0; it < 4; it++) {
        const int f = it * 32 + g;
        float2 z[16];
        #pragma unroll
        for (int n1 = 0; n1 < 8; n1++) {          // rows >= 128 are zero pad
            const int row = n1 * 16 + j;
            if (f == 0) z[n1] = make_float2(tile[row * TP].x, tile[row * TP + 128].x);
            else        z[n1] = tile[row * TP + f];
        }
        fft256_grp<-1, false, true>(z, sc, j);     // forward along column

        if (f == 0) {
            float2 o_[16];                         // snapshot (mirror needs pre-mult)
            #pragma unroll
            for (int q = 0; q < 16; q++) o_[q] = z[q];
            #pragma unroll
            for (int k2 = 0; k2 < 16; k2++) {
                const int p = P16(k2);
                const float2 om = o_[P16(15 - k2)];
                float mr_ = __shfl_sync(0xffffu, om.x, (16 - j) & 15, 16);
                float mi_ = __shfl_sync(0xffffu, om.y, (16 - j) & 15, 16);
                if (j == 0) { const float2 o0 = o_[P16((16 - k2) & 15)]; mr_ = o0.x; mi_ = o0.y; }
                const float Ar = 0.5f * (o_[p].x + mr_), Ai = 0.5f * (o_[p].y - mi_);
                const float Br = 0.5f * (o_[p].y + mi_), Bi = 0.5f * (mr_ - o_[p].x);
                const float2 k0 = g_Kf[(c * NF +   0) * 256 + k2*16 + j];
                const float2 kn = g_Kf[(c * NF + 128) * 256 + k2*16 + j];
                const float Cr = Ar * k0.x - Ai * k0.y, Ci = Ar * k0.y + Ai * k0.x;
                const float Dr = Br * kn.x - Bi * kn.y, Di = Br * kn.y + Bi * kn.x;
                z[p] = make_float2(Cr - Di, Ci + Dr);   // repack: Y = C + i*D
            }
        } else {
            const int kb = (c * NF + f) * 256;
            #pragma unroll
            for (int k2 = 0; k2 < 16; k2++) {
                const float2 kv = g_Kf[kb + k2*16 + j];
                const int p = P16(k2);
                const float a = z[p].x, b = z[p].y;
                z[p] = make_float2(a * kv.x - b * kv.y, a * kv.y + b * kv.x);
            }
        }
        fft256_grp<1, true, false>(z, sc, j);      // unnormalized inverse (PIN)
        if (f == 0) {
            #pragma unroll
            for (int k2 = 0; k2 < 8; k2++) {       // keep rows 0..127; cols real
                const int row = k2 * 16 + j;
                tile[row * TP]       = make_float2(z[P16(k2)].x, 0.f);
                tile[row * TP + 128] = make_float2(z[P16(k2)].y, 0.f);
            }
        } else {
            #pragma unroll
            for (int k2 = 0; k2 < 8; k2++) {
                const int row = k2 * 16 + j;
                tile[row * TP + f] = z[P16(k2)];
            }
        }
    }
    __syncthreads();

    // ---- Phase 3: 64 packed hermitian row inverses + residual, 2 iters ----
    #pragma unroll 1
    for (int it = 0; it < 2; it++) {
        const int rA = it * 32 + g, rB = rA + 64;
        const int baseA = rA * TP, baseB = rB * TP;
        float2 z[16];
        #pragma unroll
        for (int n1 = 0; n1 < 16; n1++) {
            const int n = n1 * 16 + j;
            float Ar, Ai, Br, Bi;
            if (n <= 128) {
                const float2 vA = tile[baseA + n], vB = tile[baseB + n];
                Ar = vA.x; Ai = vA.y; Br = vB.x; Bi = vB.y;
            } else {
                const int m2 = 256 - n;            // hermitian mirror
                const float2 vA = tile[baseA + m2], vB = tile[baseB + m2];
                Ar = vA.x; Ai = -vA.y; Br = vB.x; Bi = -vB.y;
            }
            z[n1] = make_float2(Ar - Bi, Ai + Br); // Z = A + i*B
        }
        fft256_grp<1, false, false>(z, sc, j);     // z[n] = a[n] + i*b[n]
        const int ga = (bc * HH + rA) * WW;
        const int gb = (bc * HH + rB) * WW;
        #pragma unroll
        for (int k2 = 0; k2 < 8; k2++) {
            const int col = k2 * 16 + j;
            out[ga + col] = z[P16(k2)].x + x[ga + col];
            out[gb + col] = z[P16(k2)].y + x[gb + col];
        }
    }
}

// ---------------------------------------------------------------------------
extern "C" void kernel_launch(void* const* d_in, const int* in_sizes, int n_in,
                              void* d_out, int out_size) {
    const float* x  = (const float*)d_in[0];
    const float* W1 = (const float*)d_in[1];
    const float* b1 = (const float*)d_in[2];
    const float* W2 = (const float*)d_in[3];
    const float* b2 = (const float*)d_in[4];
    float* out = (float*)d_out;

    static int smem_set = 0;
    if (!smem_set) {
        cudaFuncSetAttribute(kprep_kernel,
                             cudaFuncAttributeMaxDynamicSharedMemorySize, SMEM_BYTES);
        cudaFuncSetAttribute(fused_kernel,
                             cudaFuncAttributeMaxDynamicSharedMemorySize, SMEM_BYTES);
        smem_set = 1;
    }

    kprep_kernel<<<CH, 512, SMEM_BYTES>>>(W1, b1, W2, b2);
    fused_kernel<<<BC, 512, SMEM_BYTES>>>(x, out);
}